// round 12
// baseline (speedup 1.0000x reference)
#include <cuda_runtime.h>
#include <math.h>

// Problem constants
#define D_CH   2048
#define LSEQ   8192
#define NST    64
#define TCH    64      // chunk length for the scan
#define NCHUNK 128     // LSEQ / TCH
#define KSPLIT 8       // gemm1 k-split
#define KCHUNK 256     // 2048 / KSPLIT

// ---------------- device scratch (static, no allocation) ----------------
__device__ float  g_dA[64 * 64];            // discretized A
__device__ float  g_inv[64 * 64];           // M^{-1} = (dA + I)/2
__device__ float  g_dBt[2048 * 64];         // dB transposed: [d][n]
__device__ float  g_Upart[KSPLIT * 8192 * 64]; // gemm1 k-split partials [p][t][n]
__device__ float  g_Ut[8192 * 64];          // reduced U: [t][n]
__device__ float  g_Ht[8192 * 64];          // H transposed: [t][n]
__device__ float  g_esum[NCHUNK * 64];
__device__ float  g_hstart[NCHUNK * 64];
__device__ float  g_delta;

// ---------------- packed fp32x2 helpers (sm_103a FFMA2) ----------------
__device__ __forceinline__ unsigned long long splat2(float x) {
    unsigned long long r;
    asm("mov.b64 %0, {%1, %1};" : "=l"(r) : "r"(__float_as_uint(x)));
    return r;
}
__device__ __forceinline__ void fma2(unsigned long long& d,
                                     unsigned long long a, unsigned long long b) {
    asm("fma.rn.f32x2 %0, %1, %2, %0;" : "+l"(d) : "l"(a), "l"(b));
}
__device__ __forceinline__ float2 unpk(unsigned long long v) {
    float2 f;
    asm("mov.b64 {%0, %1}, %2;" : "=f"(f.x), "=f"(f.y) : "l"(v));
    return f;
}

// ---------------- 1) prep: fp64 in-place Gauss-Jordan inverse in SMEM ----------------
// M = I - d/2 A.  dA = M^{-1}(I + d/2 A) = 2 M^{-1} - I;  inv = M^{-1}.
// M is strongly diagonally dominant -> no pivoting needed.
__global__ __launch_bounds__(256) void prep_kernel(const float* __restrict__ A,
                                                   const float* __restrict__ logd)
{
    __shared__ double sM[64 * 65];
    __shared__ double fac_s[64];
    int tid = threadIdx.x;
    double delta = exp((double)logd[0]);

    for (int idx = tid; idx < 4096; idx += 256) {
        int i = idx >> 6, j = idx & 63;
        sM[i * 65 + j] = (i == j ? 1.0 : 0.0) - 0.5 * delta * (double)A[idx];
    }
    __syncthreads();

    for (int k = 0; k < 64; k++) {
        if (tid < 64) fac_s[tid] = sM[tid * 65 + k];   // old column k
        __syncthreads();
        double piv = 1.0 / fac_s[k];
        if (tid < 64) sM[k * 65 + tid] = (tid == k) ? piv : sM[k * 65 + tid] * piv;
        __syncthreads();
        int i = tid & 63, jg = tid >> 6;               // 4 j-groups of 16
        if (i != k) {
            double f = fac_s[i];
#pragma unroll
            for (int q = 0; q < 16; q++) {
                int j = jg * 16 + q;
                double cur = sM[i * 65 + j];
                sM[i * 65 + j] = (j == k) ? (-f * piv) : (cur - f * sM[k * 65 + j]);
            }
        }
        __syncthreads();
    }

    for (int idx = tid; idx < 4096; idx += 256) {
        int i = idx >> 6, j = idx & 63;
        double minv = sM[i * 65 + j];
        g_inv[idx] = (float)minv;
        g_dA[idx]  = (float)(2.0 * minv - (i == j ? 1.0 : 0.0));
    }
    if (tid == 0) g_delta = (float)delta;
}

// ---------------- 2) dB^T[d][n] = delta * (inv @ B)^T ----------------
__global__ __launch_bounds__(256) void dB_kernel(const float* __restrict__ B)
{
    __shared__ float inv_s[64 * 64];
    int tid = threadIdx.x;
    for (int idx = tid; idx < 4096; idx += 256) inv_s[idx] = g_inv[idx];
    __syncthreads();

    float delta = g_delta;
    int d  = blockIdx.x * 64 + (tid & 63);
    int n0 = (tid >> 6) * 16;

    float acc[16];
#pragma unroll
    for (int q = 0; q < 16; q++) acc[q] = 0.f;

    for (int k = 0; k < 64; k++) {
        float b = B[k * 2048 + d];
#pragma unroll
        for (int q = 0; q < 16; q++) acc[q] += inv_s[(n0 + q) * 64 + k] * b;
    }
#pragma unroll
    for (int q = 0; q < 16; q++) g_dBt[d * 64 + n0 + q] = delta * acc[q];
}

// ---------------- 3) GEMM1: Upart[p][t][n] = (dB @ X)^T over k-chunk p ----------------
// grid (64 t-blocks, KSPLIT), 128 threads, tile 64n x 128t, 8x8 per thread, f32x2.
__global__ __launch_bounds__(128) void gemm1_kernel(const float* __restrict__ X)
{
    __shared__ __align__(16) float sB[32 * 64];   // [kk][n]
    __shared__ __align__(16) float sX[32 * 128];  // [kk][t]
    int tid = threadIdx.x;
    int t0  = blockIdx.x * 128;
    int kbase = blockIdx.y * KCHUNK;
    int tx = tid & 15;        // t-group: 8 t each
    int ty = tid >> 4;        // n-group: 8 n each (0..7)

    unsigned long long acc[8][4];
#pragma unroll
    for (int r = 0; r < 8; r++)
#pragma unroll
        for (int c = 0; c < 4; c++) acc[r][c] = 0ull;

    for (int d0 = kbase; d0 < kbase + KCHUNK; d0 += 32) {
#pragma unroll
        for (int f = tid; f < 512; f += 128) {
            int kk = f >> 4, n4 = f & 15;
            ((float4*)sB)[f] = *(const float4*)(g_dBt + (d0 + kk) * 64 + n4 * 4);
        }
#pragma unroll
        for (int f = tid; f < 1024; f += 128) {
            int kk = f >> 5, c4 = f & 31;
            ((float4*)sX)[f] = *(const float4*)(X + (size_t)(d0 + kk) * 8192 + t0 + c4 * 4);
        }
        __syncthreads();

#pragma unroll 4
        for (int kk = 0; kk < 32; kk++) {
            float4 a0 = *(const float4*)(sB + kk * 64 + ty * 8);
            float4 a1 = *(const float4*)(sB + kk * 64 + ty * 8 + 4);
            ulonglong2 b01 = *(const ulonglong2*)(sX + kk * 128 + tx * 8);
            ulonglong2 b23 = *(const ulonglong2*)(sX + kk * 128 + tx * 8 + 4);
            unsigned long long bv[4] = {b01.x, b01.y, b23.x, b23.y};
            unsigned long long pa[8];
            pa[0] = splat2(a0.x); pa[1] = splat2(a0.y);
            pa[2] = splat2(a0.z); pa[3] = splat2(a0.w);
            pa[4] = splat2(a1.x); pa[5] = splat2(a1.y);
            pa[6] = splat2(a1.z); pa[7] = splat2(a1.w);
#pragma unroll
            for (int r = 0; r < 8; r++)
#pragma unroll
                for (int c = 0; c < 4; c++) fma2(acc[r][c], pa[r], bv[c]);
        }
        __syncthreads();
    }

    // write partial: [t][n], n contiguous
#pragma unroll
    for (int c = 0; c < 4; c++) {
        float lo[8], hi[8];
#pragma unroll
        for (int r = 0; r < 8; r++) {
            float2 f = unpk(acc[r][c]);
            lo[r] = f.x; hi[r] = f.y;
        }
        int t = t0 + tx * 8 + c * 2;
        float* dst = g_Upart + (size_t)blockIdx.y * (8192 * 64) + (size_t)t * 64 + ty * 8;
        *(float4*)(dst)      = make_float4(lo[0], lo[1], lo[2], lo[3]);
        *(float4*)(dst + 4)  = make_float4(lo[4], lo[5], lo[6], lo[7]);
        *(float4*)(dst + 64) = make_float4(hi[0], hi[1], hi[2], hi[3]);
        *(float4*)(dst + 68) = make_float4(hi[4], hi[5], hi[6], hi[7]);
    }
}

// ---------------- 4a) pass A: reduce k-split partials, local scans (h0=0) ----------------
__global__ __launch_bounds__(256) void scan_passA()
{
    __shared__ float h_s[64];
    __shared__ float partial[4][64];
    __shared__ float u_s[64 * 64];
    int tid = threadIdx.x, c = blockIdx.x;
    int part = tid >> 6, i = tid & 63;

    float a[16];
#pragma unroll
    for (int q = 0; q < 16; q++) a[q] = g_dA[i * 64 + part * 16 + q];

    for (int idx = tid; idx < 4096; idx += 256) {
        float s = 0.f;
#pragma unroll
        for (int p = 0; p < KSPLIT; p++) s += g_Upart[(size_t)p * (8192 * 64) + c * 4096 + idx];
        u_s[idx] = s;
        g_Ut[c * 4096 + idx] = s;     // reduced U for pass C
    }
    if (tid < 64) h_s[tid] = 0.f;
    __syncthreads();

    for (int j = 0; j < TCH; j++) {
        float s0 = 0.f, s1 = 0.f, s2 = 0.f, s3 = 0.f;
#pragma unroll
        for (int q = 0; q < 4; q++) {
            s0 += a[q]      * h_s[part * 16 + q];
            s1 += a[q + 4]  * h_s[part * 16 + q + 4];
            s2 += a[q + 8]  * h_s[part * 16 + q + 8];
            s3 += a[q + 12] * h_s[part * 16 + q + 12];
        }
        partial[part][i] = (s0 + s1) + (s2 + s3);
        __syncthreads();
        if (tid < 64)
            h_s[tid] = partial[0][tid] + partial[1][tid] + partial[2][tid] + partial[3][tid]
                       + u_s[j * 64 + tid];
        __syncthreads();
    }
    if (tid < 64) g_esum[c * 64 + tid] = h_s[tid];
}

// ---------------- 4b) pass B: dA^64 via squaring + boundary combine ----------------
__global__ __launch_bounds__(256) void scan_passB()
{
    __shared__ float buf0[64 * 64];
    __shared__ float buf1[64 * 64];
    __shared__ float h_s[64];
    __shared__ float partial[4][64];
    int tid = threadIdx.x;

    for (int idx = tid; idx < 4096; idx += 256) buf0[idx] = g_dA[idx];
    __syncthreads();

    float* in  = buf0;
    float* out = buf1;
    int ty = tid >> 4, tx = tid & 15;

    for (int s = 0; s < 6; s++) {              // dA^2 ... dA^64
        float acc[4][4];
#pragma unroll
        for (int r = 0; r < 4; r++)
#pragma unroll
            for (int j = 0; j < 4; j++) acc[r][j] = 0.f;
        for (int k = 0; k < 64; k++) {
            float bv[4];
#pragma unroll
            for (int j = 0; j < 4; j++) bv[j] = in[k * 64 + tx * 4 + j];
#pragma unroll
            for (int r = 0; r < 4; r++) {
                float av = in[(ty * 4 + r) * 64 + k];
#pragma unroll
                for (int j = 0; j < 4; j++) acc[r][j] += av * bv[j];
            }
        }
#pragma unroll
        for (int r = 0; r < 4; r++)
#pragma unroll
            for (int j = 0; j < 4; j++)
                out[(ty * 4 + r) * 64 + tx * 4 + j] = acc[r][j];
        __syncthreads();
        float* tmp = in; in = out; out = tmp;
    }

    int part = tid >> 6, i = tid & 63;
    float a[16];
#pragma unroll
    for (int q = 0; q < 16; q++) a[q] = in[i * 64 + part * 16 + q];
    if (tid < 64) h_s[tid] = 0.f;
    __syncthreads();

    for (int c = 0; c < NCHUNK; c++) {
        if (tid < 64) g_hstart[c * 64 + tid] = h_s[tid];
        float s0 = 0.f, s1 = 0.f, s2 = 0.f, s3 = 0.f;
#pragma unroll
        for (int q = 0; q < 4; q++) {
            s0 += a[q]      * h_s[part * 16 + q];
            s1 += a[q + 4]  * h_s[part * 16 + q + 4];
            s2 += a[q + 8]  * h_s[part * 16 + q + 8];
            s3 += a[q + 12] * h_s[part * 16 + q + 12];
        }
        partial[part][i] = (s0 + s1) + (s2 + s3);
        __syncthreads();
        if (tid < 64)
            h_s[tid] = partial[0][tid] + partial[1][tid] + partial[2][tid] + partial[3][tid]
                       + g_esum[c * 64 + tid];
        __syncthreads();
    }
}

// ---------------- 4c) pass C: local scans with correct h0, write H ----------------
__global__ __launch_bounds__(256) void scan_passC()
{
    __shared__ float h_s[64];
    __shared__ float partial[4][64];
    __shared__ float u_s[64 * 64];
    int tid = threadIdx.x, c = blockIdx.x;
    int part = tid >> 6, i = tid & 63;

    float a[16];
#pragma unroll
    for (int q = 0; q < 16; q++) a[q] = g_dA[i * 64 + part * 16 + q];
    for (int idx = tid; idx < 4096; idx += 256) u_s[idx] = g_Ut[c * 4096 + idx];
    if (tid < 64) h_s[tid] = g_hstart[c * 64 + tid];
    __syncthreads();

    for (int j = 0; j < TCH; j++) {
        float s0 = 0.f, s1 = 0.f, s2 = 0.f, s3 = 0.f;
#pragma unroll
        for (int q = 0; q < 4; q++) {
            s0 += a[q]      * h_s[part * 16 + q];
            s1 += a[q + 4]  * h_s[part * 16 + q + 4];
            s2 += a[q + 8]  * h_s[part * 16 + q + 8];
            s3 += a[q + 12] * h_s[part * 16 + q + 12];
        }
        partial[part][i] = (s0 + s1) + (s2 + s3);
        __syncthreads();
        if (tid < 64) {
            float hn = partial[0][tid] + partial[1][tid] + partial[2][tid] + partial[3][tid]
                       + u_s[j * 64 + tid];
            h_s[tid] = hn;
            g_Ht[c * 4096 + j * 64 + tid] = hn;
        }
        __syncthreads();
    }
}

// ---------------- 5) GEMM2: Y = C @ H + Dp * X, 128x128 tiles, f32x2 ----------------
__global__ __launch_bounds__(256) void gemm2_kernel(const float* __restrict__ X,
                                                    const float* __restrict__ C,
                                                    const float* __restrict__ Dp,
                                                    float* __restrict__ Y)
{
    __shared__ __align__(16) float sC[32 * 136];  // [k][d], padded
    __shared__ __align__(16) float sH[32 * 136];  // [k][t], padded
    int tid = threadIdx.x;
    int t0 = blockIdx.x * 128, d0 = blockIdx.y * 128;
    int tx = tid & 15;      // t-group, 8 t each
    int ty = tid >> 4;      // d-group, 8 d each (0..15)

    unsigned long long acc[8][4];
#pragma unroll
    for (int r = 0; r < 8; r++)
#pragma unroll
        for (int c = 0; c < 4; c++) acc[r][c] = 0ull;

    for (int kb = 0; kb < 64; kb += 32) {
        for (int idx = tid; idx < 4096; idx += 256) {
            int dd = idx >> 5, k = idx & 31;
            sC[k * 136 + dd] = C[(d0 + dd) * 64 + kb + k];
            sH[k * 136 + dd] = g_Ht[(size_t)(t0 + dd) * 64 + kb + k];
        }
        __syncthreads();

#pragma unroll 4
        for (int k = 0; k < 32; k++) {
            float4 a0 = *(const float4*)(sC + k * 136 + ty * 8);
            float4 a1 = *(const float4*)(sC + k * 136 + ty * 8 + 4);
            ulonglong2 b01 = *(const ulonglong2*)(sH + k * 136 + tx * 8);
            ulonglong2 b23 = *(const ulonglong2*)(sH + k * 136 + tx * 8 + 4);
            unsigned long long bv[4] = {b01.x, b01.y, b23.x, b23.y};
            unsigned long long pa[8];
            pa[0] = splat2(a0.x); pa[1] = splat2(a0.y);
            pa[2] = splat2(a0.z); pa[3] = splat2(a0.w);
            pa[4] = splat2(a1.x); pa[5] = splat2(a1.y);
            pa[6] = splat2(a1.z); pa[7] = splat2(a1.w);
#pragma unroll
            for (int r = 0; r < 8; r++)
#pragma unroll
                for (int c = 0; c < 4; c++) fma2(acc[r][c], pa[r], bv[c]);
        }
        __syncthreads();
    }

#pragma unroll
    for (int r = 0; r < 8; r++) {
        int d = d0 + ty * 8 + r;
        float dp = Dp[d];
        const float4 x0 = *(const float4*)(X + (size_t)d * LSEQ + t0 + tx * 8);
        const float4 x1 = *(const float4*)(X + (size_t)d * LSEQ + t0 + tx * 8 + 4);
        float2 p0 = unpk(acc[r][0]);
        float2 p1 = unpk(acc[r][1]);
        float2 p2 = unpk(acc[r][2]);
        float2 p3 = unpk(acc[r][3]);
        float4 o0 = make_float4(p0.x + dp * x0.x, p0.y + dp * x0.y,
                                p1.x + dp * x0.z, p1.y + dp * x0.w);
        float4 o1 = make_float4(p2.x + dp * x1.x, p2.y + dp * x1.y,
                                p3.x + dp * x1.z, p3.y + dp * x1.w);
        *(float4*)(Y + (size_t)d * LSEQ + t0 + tx * 8)     = o0;
        *(float4*)(Y + (size_t)d * LSEQ + t0 + tx * 8 + 4) = o1;
    }
}

// ---------------- launch ----------------
extern "C" void kernel_launch(void* const* d_in, const int* in_sizes, int n_in,
                              void* d_out, int out_size)
{
    const float* X    = (const float*)d_in[0];   // (2048, 8192)
    const float* A    = (const float*)d_in[1];   // (64, 64)
    const float* B    = (const float*)d_in[2];   // (64, 2048)
    const float* C    = (const float*)d_in[3];   // (2048, 64)
    const float* Dp   = (const float*)d_in[4];   // (2048,)
    const float* logd = (const float*)d_in[5];   // (1,)
    float* Y = (float*)d_out;                    // (2048, 8192)

    prep_kernel<<<1, 256>>>(A, logd);
    dB_kernel<<<32, 256>>>(B);
    gemm1_kernel<<<dim3(64, KSPLIT), 128>>>(X);
    scan_passA<<<NCHUNK, 256>>>();
    scan_passB<<<1, 256>>>();
    scan_passC<<<NCHUNK, 256>>>();
    gemm2_kernel<<<dim3(LSEQ / 128, D_CH / 128), 256>>>(X, C, Dp, Y);
}

// round 13
// speedup vs baseline: 1.0012x; 1.0012x over previous
#include <cuda_runtime.h>
#include <math.h>

// Problem constants
#define D_CH   2048
#define LSEQ   8192
#define NST    64
#define TCH    64      // chunk length for the scan
#define NCHUNK 128     // LSEQ / TCH
#define KSPLIT 8       // gemm1 k-split
#define KCHUNK 256     // 2048 / KSPLIT

// ---------------- device scratch (static, no allocation) ----------------
__device__ float  g_dA[64 * 64];            // discretized A
__device__ float  g_inv[64 * 64];           // M^{-1} = (dA + I)/2
__device__ float  g_dBt[2048 * 64];         // dB transposed: [d][n]
__device__ float  g_Upart[KSPLIT * 8192 * 64]; // gemm1 k-split partials [p][t][n]
__device__ float  g_Ut[8192 * 64];          // reduced U: [t][n]
__device__ float  g_Ht[8192 * 64];          // H transposed: [t][n]
__device__ float  g_esum[NCHUNK * 64];
__device__ float  g_hstart[NCHUNK * 64];
__device__ float  g_delta;

// ---------------- packed fp32x2 helpers (sm_103a FFMA2) ----------------
__device__ __forceinline__ unsigned long long splat2(float x) {
    unsigned long long r;
    asm("mov.b64 %0, {%1, %1};" : "=l"(r) : "r"(__float_as_uint(x)));
    return r;
}
__device__ __forceinline__ void fma2(unsigned long long& d,
                                     unsigned long long a, unsigned long long b) {
    asm("fma.rn.f32x2 %0, %1, %2, %0;" : "+l"(d) : "l"(a), "l"(b));
}
__device__ __forceinline__ float2 unpk(unsigned long long v) {
    float2 f;
    asm("mov.b64 {%0, %1}, %2;" : "=f"(f.x), "=f"(f.y) : "l"(v));
    return f;
}

// ---------------- 1) prep: fp64 in-place Gauss-Jordan inverse in SMEM ----------------
// M = I - d/2 A.  dA = M^{-1}(I + d/2 A) = 2 M^{-1} - I;  inv = M^{-1}.
// M is strongly diagonally dominant -> no pivoting needed.
__global__ __launch_bounds__(256) void prep_kernel(const float* __restrict__ A,
                                                   const float* __restrict__ logd)
{
    __shared__ double sM[64 * 65];
    __shared__ double fac_s[64];
    int tid = threadIdx.x;
    double delta = exp((double)logd[0]);

    for (int idx = tid; idx < 4096; idx += 256) {
        int i = idx >> 6, j = idx & 63;
        sM[i * 65 + j] = (i == j ? 1.0 : 0.0) - 0.5 * delta * (double)A[idx];
    }
    __syncthreads();

    for (int k = 0; k < 64; k++) {
        if (tid < 64) fac_s[tid] = sM[tid * 65 + k];   // old column k
        __syncthreads();
        double piv = 1.0 / fac_s[k];
        if (tid < 64) sM[k * 65 + tid] = (tid == k) ? piv : sM[k * 65 + tid] * piv;
        __syncthreads();
        int i = tid & 63, jg = tid >> 6;               // 4 j-groups of 16
        if (i != k) {
            double f = fac_s[i];
#pragma unroll
            for (int q = 0; q < 16; q++) {
                int j = jg * 16 + q;
                double cur = sM[i * 65 + j];
                sM[i * 65 + j] = (j == k) ? (-f * piv) : (cur - f * sM[k * 65 + j]);
            }
        }
        __syncthreads();
    }

    for (int idx = tid; idx < 4096; idx += 256) {
        int i = idx >> 6, j = idx & 63;
        double minv = sM[i * 65 + j];
        g_inv[idx] = (float)minv;
        g_dA[idx]  = (float)(2.0 * minv - (i == j ? 1.0 : 0.0));
    }
    if (tid == 0) g_delta = (float)delta;
}

// ---------------- 2) dB^T[d][n] = delta * (inv @ B)^T ----------------
__global__ __launch_bounds__(256) void dB_kernel(const float* __restrict__ B)
{
    __shared__ float inv_s[64 * 64];
    int tid = threadIdx.x;
    for (int idx = tid; idx < 4096; idx += 256) inv_s[idx] = g_inv[idx];
    __syncthreads();

    float delta = g_delta;
    int d  = blockIdx.x * 64 + (tid & 63);
    int n0 = (tid >> 6) * 16;

    float acc[16];
#pragma unroll
    for (int q = 0; q < 16; q++) acc[q] = 0.f;

    for (int k = 0; k < 64; k++) {
        float b = B[k * 2048 + d];
#pragma unroll
        for (int q = 0; q < 16; q++) acc[q] += inv_s[(n0 + q) * 64 + k] * b;
    }
#pragma unroll
    for (int q = 0; q < 16; q++) g_dBt[d * 64 + n0 + q] = delta * acc[q];
}

// ---------------- 3) GEMM1: Upart[p][t][n] = (dB @ X)^T over k-chunk p ----------------
// grid (64 t-blocks, KSPLIT), 128 threads, tile 64n x 128t, 8x8 per thread, f32x2.
__global__ __launch_bounds__(128) void gemm1_kernel(const float* __restrict__ X)
{
    __shared__ __align__(16) float sB[32 * 64];   // [kk][n]
    __shared__ __align__(16) float sX[32 * 128];  // [kk][t]
    int tid = threadIdx.x;
    int t0  = blockIdx.x * 128;
    int kbase = blockIdx.y * KCHUNK;
    int tx = tid & 15;        // t-group: 8 t each
    int ty = tid >> 4;        // n-group: 8 n each (0..7)

    unsigned long long acc[8][4];
#pragma unroll
    for (int r = 0; r < 8; r++)
#pragma unroll
        for (int c = 0; c < 4; c++) acc[r][c] = 0ull;

    for (int d0 = kbase; d0 < kbase + KCHUNK; d0 += 32) {
#pragma unroll
        for (int f = tid; f < 512; f += 128) {
            int kk = f >> 4, n4 = f & 15;
            ((float4*)sB)[f] = *(const float4*)(g_dBt + (d0 + kk) * 64 + n4 * 4);
        }
#pragma unroll
        for (int f = tid; f < 1024; f += 128) {
            int kk = f >> 5, c4 = f & 31;
            ((float4*)sX)[f] = *(const float4*)(X + (size_t)(d0 + kk) * 8192 + t0 + c4 * 4);
        }
        __syncthreads();

#pragma unroll 4
        for (int kk = 0; kk < 32; kk++) {
            float4 a0 = *(const float4*)(sB + kk * 64 + ty * 8);
            float4 a1 = *(const float4*)(sB + kk * 64 + ty * 8 + 4);
            ulonglong2 b01 = *(const ulonglong2*)(sX + kk * 128 + tx * 8);
            ulonglong2 b23 = *(const ulonglong2*)(sX + kk * 128 + tx * 8 + 4);
            unsigned long long bv[4] = {b01.x, b01.y, b23.x, b23.y};
            unsigned long long pa[8];
            pa[0] = splat2(a0.x); pa[1] = splat2(a0.y);
            pa[2] = splat2(a0.z); pa[3] = splat2(a0.w);
            pa[4] = splat2(a1.x); pa[5] = splat2(a1.y);
            pa[6] = splat2(a1.z); pa[7] = splat2(a1.w);
#pragma unroll
            for (int r = 0; r < 8; r++)
#pragma unroll
                for (int c = 0; c < 4; c++) fma2(acc[r][c], pa[r], bv[c]);
        }
        __syncthreads();
    }

    // write partial: [t][n], n contiguous
#pragma unroll
    for (int c = 0; c < 4; c++) {
        float lo[8], hi[8];
#pragma unroll
        for (int r = 0; r < 8; r++) {
            float2 f = unpk(acc[r][c]);
            lo[r] = f.x; hi[r] = f.y;
        }
        int t = t0 + tx * 8 + c * 2;
        float* dst = g_Upart + (size_t)blockIdx.y * (8192 * 64) + (size_t)t * 64 + ty * 8;
        *(float4*)(dst)      = make_float4(lo[0], lo[1], lo[2], lo[3]);
        *(float4*)(dst + 4)  = make_float4(lo[4], lo[5], lo[6], lo[7]);
        *(float4*)(dst + 64) = make_float4(hi[0], hi[1], hi[2], hi[3]);
        *(float4*)(dst + 68) = make_float4(hi[4], hi[5], hi[6], hi[7]);
    }
}

// ---------------- 4a) pass A: reduce k-split partials, local scans (h0=0) ----------------
__global__ __launch_bounds__(256) void scan_passA()
{
    __shared__ float h_s[64];
    __shared__ float partial[4][64];
    __shared__ float u_s[64 * 64];
    int tid = threadIdx.x, c = blockIdx.x;
    int part = tid >> 6, i = tid & 63;

    float a[16];
#pragma unroll
    for (int q = 0; q < 16; q++) a[q] = g_dA[i * 64 + part * 16 + q];

    for (int idx = tid; idx < 4096; idx += 256) {
        float s = 0.f;
#pragma unroll
        for (int p = 0; p < KSPLIT; p++) s += g_Upart[(size_t)p * (8192 * 64) + c * 4096 + idx];
        u_s[idx] = s;
        g_Ut[c * 4096 + idx] = s;     // reduced U for pass C
    }
    if (tid < 64) h_s[tid] = 0.f;
    __syncthreads();

    for (int j = 0; j < TCH; j++) {
        float s0 = 0.f, s1 = 0.f, s2 = 0.f, s3 = 0.f;
#pragma unroll
        for (int q = 0; q < 4; q++) {
            s0 += a[q]      * h_s[part * 16 + q];
            s1 += a[q + 4]  * h_s[part * 16 + q + 4];
            s2 += a[q + 8]  * h_s[part * 16 + q + 8];
            s3 += a[q + 12] * h_s[part * 16 + q + 12];
        }
        partial[part][i] = (s0 + s1) + (s2 + s3);
        __syncthreads();
        if (tid < 64)
            h_s[tid] = partial[0][tid] + partial[1][tid] + partial[2][tid] + partial[3][tid]
                       + u_s[j * 64 + tid];
        __syncthreads();
    }
    if (tid < 64) g_esum[c * 64 + tid] = h_s[tid];
}

// ---------------- 4b) pass B: dA^64 via squaring + boundary combine ----------------
__global__ __launch_bounds__(256) void scan_passB()
{
    __shared__ float buf0[64 * 64];
    __shared__ float buf1[64 * 64];
    __shared__ float h_s[64];
    __shared__ float partial[4][64];
    int tid = threadIdx.x;

    for (int idx = tid; idx < 4096; idx += 256) buf0[idx] = g_dA[idx];
    __syncthreads();

    float* in  = buf0;
    float* out = buf1;
    int ty = tid >> 4, tx = tid & 15;

    for (int s = 0; s < 6; s++) {              // dA^2 ... dA^64
        float acc[4][4];
#pragma unroll
        for (int r = 0; r < 4; r++)
#pragma unroll
            for (int j = 0; j < 4; j++) acc[r][j] = 0.f;
        for (int k = 0; k < 64; k++) {
            float bv[4];
#pragma unroll
            for (int j = 0; j < 4; j++) bv[j] = in[k * 64 + tx * 4 + j];
#pragma unroll
            for (int r = 0; r < 4; r++) {
                float av = in[(ty * 4 + r) * 64 + k];
#pragma unroll
                for (int j = 0; j < 4; j++) acc[r][j] += av * bv[j];
            }
        }
#pragma unroll
        for (int r = 0; r < 4; r++)
#pragma unroll
            for (int j = 0; j < 4; j++)
                out[(ty * 4 + r) * 64 + tx * 4 + j] = acc[r][j];
        __syncthreads();
        float* tmp = in; in = out; out = tmp;
    }

    int part = tid >> 6, i = tid & 63;
    float a[16];
#pragma unroll
    for (int q = 0; q < 16; q++) a[q] = in[i * 64 + part * 16 + q];
    if (tid < 64) h_s[tid] = 0.f;
    __syncthreads();

    for (int c = 0; c < NCHUNK; c++) {
        if (tid < 64) g_hstart[c * 64 + tid] = h_s[tid];
        float s0 = 0.f, s1 = 0.f, s2 = 0.f, s3 = 0.f;
#pragma unroll
        for (int q = 0; q < 4; q++) {
            s0 += a[q]      * h_s[part * 16 + q];
            s1 += a[q + 4]  * h_s[part * 16 + q + 4];
            s2 += a[q + 8]  * h_s[part * 16 + q + 8];
            s3 += a[q + 12] * h_s[part * 16 + q + 12];
        }
        partial[part][i] = (s0 + s1) + (s2 + s3);
        __syncthreads();
        if (tid < 64)
            h_s[tid] = partial[0][tid] + partial[1][tid] + partial[2][tid] + partial[3][tid]
                       + g_esum[c * 64 + tid];
        __syncthreads();
    }
}

// ---------------- 4c) pass C: local scans with correct h0, write H ----------------
__global__ __launch_bounds__(256) void scan_passC()
{
    __shared__ float h_s[64];
    __shared__ float partial[4][64];
    __shared__ float u_s[64 * 64];
    int tid = threadIdx.x, c = blockIdx.x;
    int part = tid >> 6, i = tid & 63;

    float a[16];
#pragma unroll
    for (int q = 0; q < 16; q++) a[q] = g_dA[i * 64 + part * 16 + q];
    for (int idx = tid; idx < 4096; idx += 256) u_s[idx] = g_Ut[c * 4096 + idx];
    if (tid < 64) h_s[tid] = g_hstart[c * 64 + tid];
    __syncthreads();

    for (int j = 0; j < TCH; j++) {
        float s0 = 0.f, s1 = 0.f, s2 = 0.f, s3 = 0.f;
#pragma unroll
        for (int q = 0; q < 4; q++) {
            s0 += a[q]      * h_s[part * 16 + q];
            s1 += a[q + 4]  * h_s[part * 16 + q + 4];
            s2 += a[q + 8]  * h_s[part * 16 + q + 8];
            s3 += a[q + 12] * h_s[part * 16 + q + 12];
        }
        partial[part][i] = (s0 + s1) + (s2 + s3);
        __syncthreads();
        if (tid < 64) {
            float hn = partial[0][tid] + partial[1][tid] + partial[2][tid] + partial[3][tid]
                       + u_s[j * 64 + tid];
            h_s[tid] = hn;
            g_Ht[c * 4096 + j * 64 + tid] = hn;
        }
        __syncthreads();
    }
}

// ---------------- 5) GEMM2: Y = C @ H + Dp * X, 128x128 tiles, f32x2 ----------------
__global__ __launch_bounds__(256) void gemm2_kernel(const float* __restrict__ X,
                                                    const float* __restrict__ C,
                                                    const float* __restrict__ Dp,
                                                    float* __restrict__ Y)
{
    __shared__ __align__(16) float sC[32 * 136];  // [k][d], padded
    __shared__ __align__(16) float sH[32 * 136];  // [k][t], padded
    int tid = threadIdx.x;
    int t0 = blockIdx.x * 128, d0 = blockIdx.y * 128;
    int tx = tid & 15;      // t-group, 8 t each
    int ty = tid >> 4;      // d-group, 8 d each (0..15)

    unsigned long long acc[8][4];
#pragma unroll
    for (int r = 0; r < 8; r++)
#pragma unroll
        for (int c = 0; c < 4; c++) acc[r][c] = 0ull;

    for (int kb = 0; kb < 64; kb += 32) {
        for (int idx = tid; idx < 4096; idx += 256) {
            int dd = idx >> 5, k = idx & 31;
            sC[k * 136 + dd] = C[(d0 + dd) * 64 + kb + k];
            sH[k * 136 + dd] = g_Ht[(size_t)(t0 + dd) * 64 + kb + k];
        }
        __syncthreads();

#pragma unroll 4
        for (int k = 0; k < 32; k++) {
            float4 a0 = *(const float4*)(sC + k * 136 + ty * 8);
            float4 a1 = *(const float4*)(sC + k * 136 + ty * 8 + 4);
            ulonglong2 b01 = *(const ulonglong2*)(sH + k * 136 + tx * 8);
            ulonglong2 b23 = *(const ulonglong2*)(sH + k * 136 + tx * 8 + 4);
            unsigned long long bv[4] = {b01.x, b01.y, b23.x, b23.y};
            unsigned long long pa[8];
            pa[0] = splat2(a0.x); pa[1] = splat2(a0.y);
            pa[2] = splat2(a0.z); pa[3] = splat2(a0.w);
            pa[4] = splat2(a1.x); pa[5] = splat2(a1.y);
            pa[6] = splat2(a1.z); pa[7] = splat2(a1.w);
#pragma unroll
            for (int r = 0; r < 8; r++)
#pragma unroll
                for (int c = 0; c < 4; c++) fma2(acc[r][c], pa[r], bv[c]);
        }
        __syncthreads();
    }

#pragma unroll
    for (int r = 0; r < 8; r++) {
        int d = d0 + ty * 8 + r;
        float dp = Dp[d];
        const float4 x0 = *(const float4*)(X + (size_t)d * LSEQ + t0 + tx * 8);
        const float4 x1 = *(const float4*)(X + (size_t)d * LSEQ + t0 + tx * 8 + 4);
        float2 p0 = unpk(acc[r][0]);
        float2 p1 = unpk(acc[r][1]);
        float2 p2 = unpk(acc[r][2]);
        float2 p3 = unpk(acc[r][3]);
        float4 o0 = make_float4(p0.x + dp * x0.x, p0.y + dp * x0.y,
                                p1.x + dp * x0.z, p1.y + dp * x0.w);
        float4 o1 = make_float4(p2.x + dp * x1.x, p2.y + dp * x1.y,
                                p3.x + dp * x1.z, p3.y + dp * x1.w);
        *(float4*)(Y + (size_t)d * LSEQ + t0 + tx * 8)     = o0;
        *(float4*)(Y + (size_t)d * LSEQ + t0 + tx * 8 + 4) = o1;
    }
}

// ---------------- launch ----------------
extern "C" void kernel_launch(void* const* d_in, const int* in_sizes, int n_in,
                              void* d_out, int out_size)
{
    const float* X    = (const float*)d_in[0];   // (2048, 8192)
    const float* A    = (const float*)d_in[1];   // (64, 64)
    const float* B    = (const float*)d_in[2];   // (64, 2048)
    const float* C    = (const float*)d_in[3];   // (2048, 64)
    const float* Dp   = (const float*)d_in[4];   // (2048,)
    const float* logd = (const float*)d_in[5];   // (1,)
    float* Y = (float*)d_out;                    // (2048, 8192)

    prep_kernel<<<1, 256>>>(A, logd);
    dB_kernel<<<32, 256>>>(B);
    gemm1_kernel<<<dim3(64, KSPLIT), 128>>>(X);
    scan_passA<<<NCHUNK, 256>>>();
    scan_passB<<<1, 256>>>();
    scan_passC<<<NCHUNK, 256>>>();
    gemm2_kernel<<<dim3(LSEQ / 128, D_CH / 128), 256>>>(X, C, Dp, Y);
}

// round 14
// speedup vs baseline: 1.0591x; 1.0578x over previous
#include <cuda_runtime.h>
#include <math.h>

// Problem constants
#define D_CH   2048
#define LSEQ   8192
#define NST    64
#define TCH    64      // chunk length for the scan
#define NCHUNK 128     // LSEQ / TCH
#define KSPLIT 8       // gemm1 k-split
#define KCHUNK 256     // 2048 / KSPLIT

// ---------------- device scratch (static, no allocation) ----------------
__device__ float  g_dA[64 * 64];            // discretized A
__device__ float  g_inv[64 * 64];           // M^{-1} = (dA + I)/2
__device__ float  g_dBt[2048 * 64];         // dB transposed: [d][n]
__device__ float  g_Upart[KSPLIT * 8192 * 64]; // gemm1 k-split partials [p][t][n]
__device__ float  g_Ut[8192 * 64];          // reduced U: [t][n]
__device__ float  g_Ht[8192 * 64];          // H transposed: [t][n]
__device__ float  g_esum[NCHUNK * 64];
__device__ float  g_hstart[NCHUNK * 64];
__device__ float  g_delta;

// ---------------- packed fp32x2 helpers (sm_103a FFMA2) ----------------
__device__ __forceinline__ unsigned long long splat2(float x) {
    unsigned long long r;
    asm("mov.b64 %0, {%1, %1};" : "=l"(r) : "r"(__float_as_uint(x)));
    return r;
}
__device__ __forceinline__ unsigned long long pack2(float x, float y) {
    unsigned long long r;
    asm("mov.b64 %0, {%1, %2};" : "=l"(r) : "r"(__float_as_uint(x)), "r"(__float_as_uint(y)));
    return r;
}
__device__ __forceinline__ void fma2(unsigned long long& d,
                                     unsigned long long a, unsigned long long b) {
    asm("fma.rn.f32x2 %0, %1, %2, %0;" : "+l"(d) : "l"(a), "l"(b));
}
__device__ __forceinline__ unsigned long long add2(unsigned long long a,
                                                   unsigned long long b) {
    unsigned long long r;
    asm("add.rn.f32x2 %0, %1, %2;" : "=l"(r) : "l"(a), "l"(b));
    return r;
}
__device__ __forceinline__ float2 unpk(unsigned long long v) {
    float2 f;
    asm("mov.b64 {%0, %1}, %2;" : "=f"(f.x), "=f"(f.y) : "l"(v));
    return f;
}
#define BAR64() asm volatile("bar.sync 1, 64;" ::: "memory")

// ---------------- 1) prep: fp64 in-place Gauss-Jordan inverse in SMEM ----------------
__global__ __launch_bounds__(256) void prep_kernel(const float* __restrict__ A,
                                                   const float* __restrict__ logd)
{
    __shared__ double sM[64 * 65];
    __shared__ double fac_s[64];
    int tid = threadIdx.x;
    double delta = exp((double)logd[0]);

    for (int idx = tid; idx < 4096; idx += 256) {
        int i = idx >> 6, j = idx & 63;
        sM[i * 65 + j] = (i == j ? 1.0 : 0.0) - 0.5 * delta * (double)A[idx];
    }
    __syncthreads();

    for (int k = 0; k < 64; k++) {
        if (tid < 64) fac_s[tid] = sM[tid * 65 + k];   // old column k
        __syncthreads();
        double piv = 1.0 / fac_s[k];
        if (tid < 64) sM[k * 65 + tid] = (tid == k) ? piv : sM[k * 65 + tid] * piv;
        __syncthreads();
        int i = tid & 63, jg = tid >> 6;               // 4 j-groups of 16
        if (i != k) {
            double f = fac_s[i];
#pragma unroll
            for (int q = 0; q < 16; q++) {
                int j = jg * 16 + q;
                double cur = sM[i * 65 + j];
                sM[i * 65 + j] = (j == k) ? (-f * piv) : (cur - f * sM[k * 65 + j]);
            }
        }
        __syncthreads();
    }

    for (int idx = tid; idx < 4096; idx += 256) {
        int i = idx >> 6, j = idx & 63;
        double minv = sM[i * 65 + j];
        g_inv[idx] = (float)minv;
        g_dA[idx]  = (float)(2.0 * minv - (i == j ? 1.0 : 0.0));
    }
    if (tid == 0) g_delta = (float)delta;
}

// ---------------- 2) dB^T[d][n] = delta * (inv @ B)^T ----------------
__global__ __launch_bounds__(256) void dB_kernel(const float* __restrict__ B)
{
    __shared__ float inv_s[64 * 64];
    int tid = threadIdx.x;
    for (int idx = tid; idx < 4096; idx += 256) inv_s[idx] = g_inv[idx];
    __syncthreads();

    float delta = g_delta;
    int d  = blockIdx.x * 64 + (tid & 63);
    int n0 = (tid >> 6) * 16;

    float acc[16];
#pragma unroll
    for (int q = 0; q < 16; q++) acc[q] = 0.f;

    for (int k = 0; k < 64; k++) {
        float b = B[k * 2048 + d];
#pragma unroll
        for (int q = 0; q < 16; q++) acc[q] += inv_s[(n0 + q) * 64 + k] * b;
    }
#pragma unroll
    for (int q = 0; q < 16; q++) g_dBt[d * 64 + n0 + q] = delta * acc[q];
}

// ---------------- 3) GEMM1: Upart[p][t][n] = (dB @ X)^T over k-chunk p ----------------
__global__ __launch_bounds__(128) void gemm1_kernel(const float* __restrict__ X)
{
    __shared__ __align__(16) float sB[32 * 64];   // [kk][n]
    __shared__ __align__(16) float sX[32 * 128];  // [kk][t]
    int tid = threadIdx.x;
    int t0  = blockIdx.x * 128;
    int kbase = blockIdx.y * KCHUNK;
    int tx = tid & 15;        // t-group: 8 t each
    int ty = tid >> 4;        // n-group: 8 n each (0..7)

    unsigned long long acc[8][4];
#pragma unroll
    for (int r = 0; r < 8; r++)
#pragma unroll
        for (int c = 0; c < 4; c++) acc[r][c] = 0ull;

    for (int d0 = kbase; d0 < kbase + KCHUNK; d0 += 32) {
#pragma unroll
        for (int f = tid; f < 512; f += 128) {
            int kk = f >> 4, n4 = f & 15;
            ((float4*)sB)[f] = *(const float4*)(g_dBt + (d0 + kk) * 64 + n4 * 4);
        }
#pragma unroll
        for (int f = tid; f < 1024; f += 128) {
            int kk = f >> 5, c4 = f & 31;
            ((float4*)sX)[f] = *(const float4*)(X + (size_t)(d0 + kk) * 8192 + t0 + c4 * 4);
        }
        __syncthreads();

#pragma unroll 4
        for (int kk = 0; kk < 32; kk++) {
            float4 a0 = *(const float4*)(sB + kk * 64 + ty * 8);
            float4 a1 = *(const float4*)(sB + kk * 64 + ty * 8 + 4);
            ulonglong2 b01 = *(const ulonglong2*)(sX + kk * 128 + tx * 8);
            ulonglong2 b23 = *(const ulonglong2*)(sX + kk * 128 + tx * 8 + 4);
            unsigned long long bv[4] = {b01.x, b01.y, b23.x, b23.y};
            unsigned long long pa[8];
            pa[0] = splat2(a0.x); pa[1] = splat2(a0.y);
            pa[2] = splat2(a0.z); pa[3] = splat2(a0.w);
            pa[4] = splat2(a1.x); pa[5] = splat2(a1.y);
            pa[6] = splat2(a1.z); pa[7] = splat2(a1.w);
#pragma unroll
            for (int r = 0; r < 8; r++)
#pragma unroll
                for (int c = 0; c < 4; c++) fma2(acc[r][c], pa[r], bv[c]);
        }
        __syncthreads();
    }

#pragma unroll
    for (int c = 0; c < 4; c++) {
        float lo[8], hi[8];
#pragma unroll
        for (int r = 0; r < 8; r++) {
            float2 f = unpk(acc[r][c]);
            lo[r] = f.x; hi[r] = f.y;
        }
        int t = t0 + tx * 8 + c * 2;
        float* dst = g_Upart + (size_t)blockIdx.y * (8192 * 64) + (size_t)t * 64 + ty * 8;
        *(float4*)(dst)      = make_float4(lo[0], lo[1], lo[2], lo[3]);
        *(float4*)(dst + 4)  = make_float4(lo[4], lo[5], lo[6], lo[7]);
        *(float4*)(dst + 64) = make_float4(hi[0], hi[1], hi[2], hi[3]);
        *(float4*)(dst + 68) = make_float4(hi[4], hi[5], hi[6], hi[7]);
    }
}

// ---------------- 3b) reduce k-split partials at full bandwidth ----------------
__global__ __launch_bounds__(256) void reduce_kernel()
{
    int f = blockIdx.x * 256 + threadIdx.x;       // float4 index, 131072 total
    const float4* src = (const float4*)g_Upart;
    float4 s = src[f];
#pragma unroll
    for (int p = 1; p < KSPLIT; p++) {
        float4 v = src[(size_t)p * 131072 + f];
        s.x += v.x; s.y += v.y; s.z += v.z; s.w += v.w;
    }
    ((float4*)g_Ut)[f] = s;
}

// ---------------- 4a) pass A: register-row local scans (h0 = 0) ----------------
// 64 scan threads, dA row i in registers (packed f32x2), ping-pong h buffer,
// one named barrier per step.
__global__ __launch_bounds__(256) void scan_passA()
{
    __shared__ __align__(16) float u_s[64 * 64];
    __shared__ __align__(16) float hb[2][64];
    int tid = threadIdx.x, c = blockIdx.x;

    for (int f = tid; f < 1024; f += 256)
        ((float4*)u_s)[f] = ((const float4*)(g_Ut + c * 4096))[f];
    if (tid < 64) hb[0][tid] = 0.f;
    __syncthreads();
    if (tid >= 64) return;

    unsigned long long a[32];
    const float4* rowp = (const float4*)(g_dA + tid * 64);
#pragma unroll
    for (int q = 0; q < 16; q++) {
        float4 v = rowp[q];
        a[2 * q]     = pack2(v.x, v.y);
        a[2 * q + 1] = pack2(v.z, v.w);
    }

    float h = 0.f;
    for (int j = 0; j < TCH; j++) {
        const unsigned long long* hp = (const unsigned long long*)hb[j & 1];
        unsigned long long acc0 = 0, acc1 = 0, acc2 = 0, acc3 = 0;
#pragma unroll
        for (int q = 0; q < 8; q++) {
            fma2(acc0, a[4 * q + 0], hp[4 * q + 0]);
            fma2(acc1, a[4 * q + 1], hp[4 * q + 1]);
            fma2(acc2, a[4 * q + 2], hp[4 * q + 2]);
            fma2(acc3, a[4 * q + 3], hp[4 * q + 3]);
        }
        float2 f = unpk(add2(add2(acc0, acc1), add2(acc2, acc3)));
        h = f.x + f.y + u_s[j * 64 + tid];
        hb[(j + 1) & 1][tid] = h;
        BAR64();
    }
    g_esum[c * 64 + tid] = h;
}

// ---------------- 4b) pass B: dA^64 via squaring + register-row combine ----------------
__global__ __launch_bounds__(256) void scan_passB()
{
    __shared__ __align__(16) float buf0[64 * 64];
    __shared__ __align__(16) float buf1[64 * 64];
    __shared__ __align__(16) float hb[2][64];
    int tid = threadIdx.x;

    for (int idx = tid; idx < 4096; idx += 256) buf0[idx] = g_dA[idx];
    __syncthreads();

    float* in  = buf0;
    float* out = buf1;
    int ty = tid >> 4, tx = tid & 15;

    for (int s = 0; s < 6; s++) {              // dA^2 ... dA^64
        float acc[4][4];
#pragma unroll
        for (int r = 0; r < 4; r++)
#pragma unroll
            for (int j = 0; j < 4; j++) acc[r][j] = 0.f;
        for (int k = 0; k < 64; k++) {
            float bv[4];
#pragma unroll
            for (int j = 0; j < 4; j++) bv[j] = in[k * 64 + tx * 4 + j];
#pragma unroll
            for (int r = 0; r < 4; r++) {
                float av = in[(ty * 4 + r) * 64 + k];
#pragma unroll
                for (int j = 0; j < 4; j++) acc[r][j] += av * bv[j];
            }
        }
#pragma unroll
        for (int r = 0; r < 4; r++)
#pragma unroll
            for (int j = 0; j < 4; j++)
                out[(ty * 4 + r) * 64 + tx * 4 + j] = acc[r][j];
        __syncthreads();
        float* tmp = in; in = out; out = tmp;
    }
    // 'in' now holds dA^64 (visible: loop ended with __syncthreads)

    if (tid >= 64) return;

    unsigned long long a[32];
#pragma unroll
    for (int q = 0; q < 16; q++) {
        float4 v = *(const float4*)(in + tid * 64 + q * 4);
        a[2 * q]     = pack2(v.x, v.y);
        a[2 * q + 1] = pack2(v.z, v.w);
    }

    float e0 = g_esum[tid];
    float e1 = g_esum[64 + tid];
    float h = 0.f;
    hb[0][tid] = 0.f;
    BAR64();

    for (int c = 0; c < NCHUNK; c++) {
        g_hstart[c * 64 + tid] = h;                       // state entering chunk c
        float en = (c + 2 < NCHUNK) ? __ldg(g_esum + (c + 2) * 64 + tid) : 0.f;
        const unsigned long long* hp = (const unsigned long long*)hb[c & 1];
        unsigned long long acc0 = 0, acc1 = 0, acc2 = 0, acc3 = 0;
#pragma unroll
        for (int q = 0; q < 8; q++) {
            fma2(acc0, a[4 * q + 0], hp[4 * q + 0]);
            fma2(acc1, a[4 * q + 1], hp[4 * q + 1]);
            fma2(acc2, a[4 * q + 2], hp[4 * q + 2]);
            fma2(acc3, a[4 * q + 3], hp[4 * q + 3]);
        }
        float2 f = unpk(add2(add2(acc0, acc1), add2(acc2, acc3)));
        h = f.x + f.y + e0;
        e0 = e1; e1 = en;
        hb[(c + 1) & 1][tid] = h;
        BAR64();
    }
}

// ---------------- 4c) pass C: register-row local scans with correct h0, write H ----------------
__global__ __launch_bounds__(256) void scan_passC()
{
    __shared__ __align__(16) float u_s[64 * 64];
    __shared__ __align__(16) float hb[2][64];
    int tid = threadIdx.x, c = blockIdx.x;

    for (int f = tid; f < 1024; f += 256)
        ((float4*)u_s)[f] = ((const float4*)(g_Ut + c * 4096))[f];
    if (tid < 64) hb[0][tid] = g_hstart[c * 64 + tid];
    __syncthreads();
    if (tid >= 64) return;

    unsigned long long a[32];
    const float4* rowp = (const float4*)(g_dA + tid * 64);
#pragma unroll
    for (int q = 0; q < 16; q++) {
        float4 v = rowp[q];
        a[2 * q]     = pack2(v.x, v.y);
        a[2 * q + 1] = pack2(v.z, v.w);
    }

    for (int j = 0; j < TCH; j++) {
        const unsigned long long* hp = (const unsigned long long*)hb[j & 1];
        unsigned long long acc0 = 0, acc1 = 0, acc2 = 0, acc3 = 0;
#pragma unroll
        for (int q = 0; q < 8; q++) {
            fma2(acc0, a[4 * q + 0], hp[4 * q + 0]);
            fma2(acc1, a[4 * q + 1], hp[4 * q + 1]);
            fma2(acc2, a[4 * q + 2], hp[4 * q + 2]);
            fma2(acc3, a[4 * q + 3], hp[4 * q + 3]);
        }
        float2 f = unpk(add2(add2(acc0, acc1), add2(acc2, acc3)));
        float h = f.x + f.y + u_s[j * 64 + tid];
        u_s[j * 64 + tid] = h;          // keep history in smem (own slot only)
        hb[(j + 1) & 1][tid] = h;
        BAR64();
    }

    // bulk-write H history (64 threads x 16 float4)
    float4* dst = (float4*)(g_Ht + c * 4096);
#pragma unroll
    for (int q = 0; q < 16; q++)
        dst[q * 64 + tid] = ((const float4*)u_s)[q * 64 + tid];
}

// ---------------- 5) GEMM2: Y = C @ H + Dp * X, 128x128 tiles, f32x2 ----------------
__global__ __launch_bounds__(256) void gemm2_kernel(const float* __restrict__ X,
                                                    const float* __restrict__ C,
                                                    const float* __restrict__ Dp,
                                                    float* __restrict__ Y)
{
    __shared__ __align__(16) float sC[32 * 136];  // [k][d], padded
    __shared__ __align__(16) float sH[32 * 136];  // [k][t], padded
    int tid = threadIdx.x;
    int t0 = blockIdx.x * 128, d0 = blockIdx.y * 128;
    int tx = tid & 15;      // t-group, 8 t each
    int ty = tid >> 4;      // d-group, 8 d each (0..15)

    unsigned long long acc[8][4];
#pragma unroll
    for (int r = 0; r < 8; r++)
#pragma unroll
        for (int c = 0; c < 4; c++) acc[r][c] = 0ull;

    for (int kb = 0; kb < 64; kb += 32) {
        for (int idx = tid; idx < 4096; idx += 256) {
            int dd = idx >> 5, k = idx & 31;
            sC[k * 136 + dd] = C[(d0 + dd) * 64 + kb + k];
            sH[k * 136 + dd] = g_Ht[(size_t)(t0 + dd) * 64 + kb + k];
        }
        __syncthreads();

#pragma unroll 4
        for (int k = 0; k < 32; k++) {
            float4 a0 = *(const float4*)(sC + k * 136 + ty * 8);
            float4 a1 = *(const float4*)(sC + k * 136 + ty * 8 + 4);
            ulonglong2 b01 = *(const ulonglong2*)(sH + k * 136 + tx * 8);
            ulonglong2 b23 = *(const ulonglong2*)(sH + k * 136 + tx * 8 + 4);
            unsigned long long bv[4] = {b01.x, b01.y, b23.x, b23.y};
            unsigned long long pa[8];
            pa[0] = splat2(a0.x); pa[1] = splat2(a0.y);
            pa[2] = splat2(a0.z); pa[3] = splat2(a0.w);
            pa[4] = splat2(a1.x); pa[5] = splat2(a1.y);
            pa[6] = splat2(a1.z); pa[7] = splat2(a1.w);
#pragma unroll
            for (int r = 0; r < 8; r++)
#pragma unroll
                for (int c = 0; c < 4; c++) fma2(acc[r][c], pa[r], bv[c]);
        }
        __syncthreads();
    }

#pragma unroll
    for (int r = 0; r < 8; r++) {
        int d = d0 + ty * 8 + r;
        float dp = Dp[d];
        const float4 x0 = *(const float4*)(X + (size_t)d * LSEQ + t0 + tx * 8);
        const float4 x1 = *(const float4*)(X + (size_t)d * LSEQ + t0 + tx * 8 + 4);
        float2 p0 = unpk(acc[r][0]);
        float2 p1 = unpk(acc[r][1]);
        float2 p2 = unpk(acc[r][2]);
        float2 p3 = unpk(acc[r][3]);
        float4 o0 = make_float4(p0.x + dp * x0.x, p0.y + dp * x0.y,
                                p1.x + dp * x0.z, p1.y + dp * x0.w);
        float4 o1 = make_float4(p2.x + dp * x1.x, p2.y + dp * x1.y,
                                p3.x + dp * x1.z, p3.y + dp * x1.w);
        *(float4*)(Y + (size_t)d * LSEQ + t0 + tx * 8)     = o0;
        *(float4*)(Y + (size_t)d * LSEQ + t0 + tx * 8 + 4) = o1;
    }
}

// ---------------- launch ----------------
extern "C" void kernel_launch(void* const* d_in, const int* in_sizes, int n_in,
                              void* d_out, int out_size)
{
    const float* X    = (const float*)d_in[0];   // (2048, 8192)
    const float* A    = (const float*)d_in[1];   // (64, 64)
    const float* B    = (const float*)d_in[2];   // (64, 2048)
    const float* C    = (const float*)d_in[3];   // (2048, 64)
    const float* Dp   = (const float*)d_in[4];   // (2048,)
    const float* logd = (const float*)d_in[5];   // (1,)
    float* Y = (float*)d_out;                    // (2048, 8192)

    prep_kernel<<<1, 256>>>(A, logd);
    dB_kernel<<<32, 256>>>(B);
    gemm1_kernel<<<dim3(64, KSPLIT), 128>>>(X);
    reduce_kernel<<<512, 256>>>();
    scan_passA<<<NCHUNK, 256>>>();
    scan_passB<<<1, 256>>>();
    scan_passC<<<NCHUNK, 256>>>();
    gemm2_kernel<<<dim3(LSEQ / 128, D_CH / 128), 256>>>(X, C, Dp, Y);
}